// round 16
// baseline (speedup 1.0000x reference)
#include <cuda_runtime.h>
#include <cuda_fp16.h>
#include <math.h>
#include <stdint.h>

#define B_ 64
#define S_ 2048
#define D_ 512

// ---------------- scratch (static device globals) ----------------
__device__ float g_dec_part[B_ * D_];
__device__ float g_score_part[4 * B_ * S_];
__device__ __align__(16) __half g_WT[D_ * D_];           // W_enc^T fp16, [n][k]
__device__ __align__(16) __half g_EncH[B_ * S_ * D_];    // enc fp16, 128 MB
__device__ float g_ctx_part[32 * B_ * D_];

// ---------------- helpers ----------------
__device__ __forceinline__ uint32_t smem_u32(const void* p) {
    uint32_t a;
    asm("{ .reg .u64 t; cvta.to.shared.u64 t, %1; cvt.u32.u64 %0, t; }"
        : "=r"(a) : "l"(p));
    return a;
}

__device__ __forceinline__ void ldsm4(uint32_t* r, uint32_t addr) {
    asm volatile("ldmatrix.sync.aligned.m8n8.x4.shared.b16 {%0,%1,%2,%3}, [%4];"
                 : "=r"(r[0]), "=r"(r[1]), "=r"(r[2]), "=r"(r[3]) : "r"(addr));
}

__device__ __forceinline__ void mma16816(float* c, const uint32_t* a,
                                         const uint32_t* b) {
    asm volatile(
        "mma.sync.aligned.m16n8k16.row.col.f32.f16.f16.f32 "
        "{%0,%1,%2,%3}, {%4,%5,%6,%7}, {%8,%9}, {%0,%1,%2,%3};"
        : "+f"(c[0]), "+f"(c[1]), "+f"(c[2]), "+f"(c[3])
        : "r"(a[0]), "r"(a[1]), "r"(a[2]), "r"(a[3]), "r"(b[0]), "r"(b[1]));
}

__device__ __forceinline__ uint32_t pack_h2(__half a, __half b) {
    __half2 t = __halves2half2(a, b);
    return *reinterpret_cast<uint32_t*>(&t);
}

#define CP_ASYNC16(dst, src) \
    asm volatile("cp.async.cg.shared.global [%0], [%1], 16;" :: "r"(dst), "l"(src))
#define CP_COMMIT()  asm volatile("cp.async.commit_group;")
#define CP_WAIT0()   asm volatile("cp.async.wait_group 0;")
#define CP_WAIT1()   asm volatile("cp.async.wait_group 1;")

// ---------------------------------------------------------------------------
// Kernel 1: dec_part[b][d] = b_t[d] + dec[b] @ W_t[:D]   (fp32, exact)
// ---------------------------------------------------------------------------
__global__ void decpart_kernel(const float* __restrict__ dec,
                               const float* __restrict__ Wt,
                               const float* __restrict__ bt) {
    __shared__ float ds[D_];
    int b = blockIdx.y;
    int d = blockIdx.x * 128 + threadIdx.x;
    for (int i = threadIdx.x; i < D_; i += 128) ds[i] = dec[b * D_ + i];
    __syncthreads();
    float acc = bt[d];
#pragma unroll 8
    for (int e = 0; e < D_; e++)
        acc = fmaf(ds[e], Wt[(size_t)e * D_ + d], acc);
    g_dec_part[b * D_ + d] = acc;
}

// ---------------------------------------------------------------------------
// Kernel 2: W_enc -> fp16, transposed to [n][k]
// ---------------------------------------------------------------------------
__global__ void wconv_kernel(const float* __restrict__ Wt) {
    int idx = blockIdx.x * 512 + threadIdx.x;  // idx = k*512 + n
    int k = idx >> 9;
    int n = idx & 511;
    g_WT[(size_t)n * D_ + k] = __float2half_rn(Wt[(size_t)(D_ + k) * D_ + n]);
}

// ---------------------------------------------------------------------------
// Kernel 2b: enc -> fp16, 8 floats (2 x float4) per thread
// ---------------------------------------------------------------------------
__global__ void encconv_kernel(const float* __restrict__ enc) {
    size_t base = (size_t)blockIdx.x * 512 + threadIdx.x;   // float4 index
#pragma unroll
    for (int j = 0; j < 2; j++) {
        size_t i4 = base + j * 256;
        float4 v = reinterpret_cast<const float4*>(enc)[i4];
        reinterpret_cast<uint2*>(g_EncH)[i4] = make_uint2(
            pack_h2(__float2half_rn(v.x), __float2half_rn(v.y)),
            pack_h2(__float2half_rn(v.z), __float2half_rn(v.w)));
    }
}

// ---------------------------------------------------------------------------
// Kernel 3: score GEMM, pure fp16 mma.sync, 3-stage cp.async ring, occ 2.
// CTA: M=128 x N=128, K=512 in 16 chunks of 32. 8 warps 2m x 4n, warp 64x32.
// (Verbatim R8/R13 — proven fastest configuration; loads issued BEFORE the
// MMA body, which R15 proved is load-bearing.)
// ---------------------------------------------------------------------------
#define STRIDE 80          // bytes per 32-elem fp16 row (64B data + 16B pad)
#define A_OFF 0
#define B_OFF 10240
#define STAGE_SZ 20480
#define DEC_OFF 61440
#define VA_OFF  63488
#define RED_OFF 65536
#define SMEM_TOTAL 67584

__global__ __launch_bounds__(256, 2)
void score_kernel(const float* __restrict__ va) {
    extern __shared__ __align__(16) char sm[];
    float* sDec = reinterpret_cast<float*>(sm + DEC_OFF);
    float* sVa  = reinterpret_cast<float*>(sm + VA_OFF);
    float* sRed = reinterpret_cast<float*>(sm + RED_OFF);

    int tid = threadIdx.x;
    int l = tid & 31;
    int w = tid >> 5;
    int warpm = w >> 2;
    int warpn = w & 3;
    int b  = blockIdx.y;
    int nc = blockIdx.x & 3;            // n-chunk (fastest -> co-scheduled)
    int s0 = (blockIdx.x >> 2) * 128;   // s-chunk

    sDec[tid]       = g_dec_part[b * D_ + tid];
    sDec[tid + 256] = g_dec_part[b * D_ + tid + 256];
    sVa[tid]        = va[tid];
    sVa[tid + 256]  = va[tid + 256];

    const __half* eh = g_EncH + ((size_t)b * S_ + s0) * D_;
    const __half* wh = g_WT + (size_t)(nc * 128) * D_;

    uint32_t smU = smem_u32(sm);
    uint32_t aOff = warpm * (64 * STRIDE) + (l & 15) * STRIDE + (l >> 4) * 16;
    uint32_t bOff = warpn * (32 * STRIDE)
                  + ((l & 7) + ((l & 16) >> 1)) * STRIDE + (l & 8) * 2;

    // per-thread cp.async: 2 chunks per tile; rows r0, r0+64; 16B col c0
    int r0 = tid >> 2;
    int r1 = r0 + 64;
    int c0 = (tid & 3) * 16;
    int k0e0 = (tid & 3) * 8;

    // ---- prologue: load stages 0 and 1 (kc = 0, 1) ----
#pragma unroll
    for (int s = 0; s < 2; s++) {
        uint32_t sb = smU + s * STAGE_SZ;
        int ke = s * 32 + k0e0;
        CP_ASYNC16(sb + A_OFF + r0 * STRIDE + c0, eh + (size_t)r0 * D_ + ke);
        CP_ASYNC16(sb + A_OFF + r1 * STRIDE + c0, eh + (size_t)r1 * D_ + ke);
        CP_ASYNC16(sb + B_OFF + r0 * STRIDE + c0, wh + (size_t)r0 * D_ + ke);
        CP_ASYNC16(sb + B_OFF + r1 * STRIDE + c0, wh + (size_t)r1 * D_ + ke);
        CP_COMMIT();
    }

    float acc[4][4][4];
#pragma unroll
    for (int mf = 0; mf < 4; mf++)
#pragma unroll
        for (int nf = 0; nf < 4; nf++)
#pragma unroll
            for (int r = 0; r < 4; r++) acc[mf][nf][r] = 0.f;

    for (int kc = 0; kc < 16; kc++) {
        if (kc < 15) { CP_WAIT1(); } else { CP_WAIT0(); }
        __syncthreads();   // stage kc%3 visible; slot (kc+2)%3 free of readers

        uint32_t curBase = smU + (kc % 3) * STAGE_SZ;

        // ---- issue loads for kc+2 into ring slot (kc+2)%3 ----
        if (kc + 2 < 16) {
            uint32_t nb = smU + ((kc + 2) % 3) * STAGE_SZ;
            int ke = (kc + 2) * 32 + k0e0;
            CP_ASYNC16(nb + A_OFF + r0 * STRIDE + c0, eh + (size_t)r0 * D_ + ke);
            CP_ASYNC16(nb + A_OFF + r1 * STRIDE + c0, eh + (size_t)r1 * D_ + ke);
            CP_ASYNC16(nb + B_OFF + r0 * STRIDE + c0, wh + (size_t)r0 * D_ + ke);
            CP_ASYNC16(nb + B_OFF + r1 * STRIDE + c0, wh + (size_t)r1 * D_ + ke);
            CP_COMMIT();
        }

        // ---- MMAs on current stage: 2 x k16 steps ----
#pragma unroll
        for (int ks = 0; ks < 2; ks++) {
            uint32_t kby = ks * 32;
            uint32_t a[4][4], bf[2][4];
#pragma unroll
            for (int mf = 0; mf < 4; mf++)
                ldsm4(a[mf], curBase + A_OFF + aOff + mf * (16 * STRIDE) + kby);
#pragma unroll
            for (int bp = 0; bp < 2; bp++)
                ldsm4(bf[bp], curBase + B_OFF + bOff + bp * (16 * STRIDE) + kby);
#pragma unroll
            for (int mf = 0; mf < 4; mf++)
#pragma unroll
                for (int nf = 0; nf < 4; nf++)
                    mma16816(acc[mf][nf], a[mf], &bf[nf >> 1][(nf & 1) * 2]);
        }
    }

    // ---- epilogue: tanh + dot v_a over this CTA's 128 d's ----
    float rp[8];
#pragma unroll
    for (int i = 0; i < 8; i++) rp[i] = 0.f;
    {
        int tig = l & 3;
#pragma unroll
        for (int mf = 0; mf < 4; mf++)
#pragma unroll
            for (int nf = 0; nf < 4; nf++)
#pragma unroll
                for (int r = 0; r < 4; r++) {
                    int d = nc * 128 + warpn * 32 + nf * 8 + tig * 2 + (r & 1);
                    float x = acc[mf][nf][r] + sDec[d];
                    float t = 1.0f - __fdividef(2.0f, __expf(2.0f * x) + 1.0f);
                    rp[mf * 2 + (r >> 1)] += t * sVa[d];
                }
    }
#pragma unroll
    for (int i = 0; i < 8; i++) {
        rp[i] += __shfl_xor_sync(0xffffffffu, rp[i], 1);
        rp[i] += __shfl_xor_sync(0xffffffffu, rp[i], 2);
    }
    __syncthreads();
    if ((l & 3) == 0) {
        int g = l >> 2;
#pragma unroll
        for (int mf = 0; mf < 4; mf++)
#pragma unroll
            for (int h = 0; h < 2; h++) {
                int row = warpm * 64 + mf * 16 + h * 8 + g;
                sRed[warpn * 128 + row] = rp[mf * 2 + h];
            }
    }
    __syncthreads();
    if (tid < 128)
        g_score_part[((size_t)nc * B_ + b) * S_ + s0 + tid] =
            sRed[tid] + sRed[128 + tid] + sRed[256 + tid] + sRed[384 + tid];
}

// ---------------------------------------------------------------------------
// Kernel 4: combine nc-partials + per-batch softmax -> alignment
// ---------------------------------------------------------------------------
__global__ void softmax_kernel(float* __restrict__ out) {
    int b = blockIdx.x;
    int t = threadIdx.x;
    __shared__ float red[16];

    float v[4];
    float mx = -1e30f;
#pragma unroll
    for (int i = 0; i < 4; i++) {
        int off = b * S_ + t + i * 512;
        v[i] = g_score_part[off]
             + g_score_part[(size_t)B_ * S_ + off]
             + g_score_part[(size_t)2 * B_ * S_ + off]
             + g_score_part[(size_t)3 * B_ * S_ + off];
        mx = fmaxf(mx, v[i]);
    }
    for (int off = 16; off > 0; off >>= 1)
        mx = fmaxf(mx, __shfl_xor_sync(0xffffffffu, mx, off));
    if ((t & 31) == 0) red[t >> 5] = mx;
    __syncthreads();
    if (t < 16) {
        float mm = red[t];
        for (int off = 8; off > 0; off >>= 1)
            mm = fmaxf(mm, __shfl_xor_sync(0xffffu, mm, off));
        red[t] = mm;
    }
    __syncthreads();
    mx = red[0];
    __syncthreads();

    float e[4], sum = 0.f;
#pragma unroll
    for (int i = 0; i < 4; i++) {
        e[i] = __expf(v[i] - mx);
        sum += e[i];
    }
    for (int off = 16; off > 0; off >>= 1)
        sum += __shfl_xor_sync(0xffffffffu, sum, off);
    if ((t & 31) == 0) red[t >> 5] = sum;
    __syncthreads();
    if (t < 16) {
        float ss = red[t];
        for (int off = 8; off > 0; off >>= 1)
            ss += __shfl_xor_sync(0xffffu, ss, off);
        red[t] = ss;
    }
    __syncthreads();
    float inv = 1.f / red[0];
#pragma unroll
    for (int i = 0; i < 4; i++)
        out[B_ * D_ + b * S_ + t + i * 512] = e[i] * inv;
}

// ---------------------------------------------------------------------------
// Kernel 5: partial context over 64-row s-chunks, __half2 loads (256 thr)
// ---------------------------------------------------------------------------
__global__ void ctx_part_kernel(const float* __restrict__ out_alpha) {
    int sc = blockIdx.x;                 // 0..31
    int b  = blockIdx.y;
    int t  = threadIdx.x;                // 256; covers d-pair 2t, 2t+1
    __shared__ float as_[64];
    if (t < 64) as_[t] = out_alpha[B_ * D_ + b * S_ + sc * 64 + t];
    __syncthreads();
    float ax = 0.f, ay = 0.f;
    const __half2* eb = reinterpret_cast<const __half2*>(
        g_EncH + ((size_t)b * S_ + sc * 64) * D_) + t;
#pragma unroll 8
    for (int s = 0; s < 64; s++) {
        float2 v = __half22float2(eb[(size_t)s * (D_ / 2)]);
        float a = as_[s];
        ax = fmaf(a, v.x, ax);
        ay = fmaf(a, v.y, ay);
    }
    float* dst = g_ctx_part + (size_t)(sc * B_ + b) * D_ + 2 * t;
    dst[0] = ax;
    dst[1] = ay;
}

// ---------------------------------------------------------------------------
// Kernel 6: combine partials, 256 threads x float2 (coalesced 8B loads)
// ---------------------------------------------------------------------------
__global__ void ctx_combine_kernel(float* __restrict__ out) {
    int b = blockIdx.x;
    int t = threadIdx.x;                 // 256; covers d-pair 2t, 2t+1
    float sx = 0.f, sy = 0.f;
#pragma unroll
    for (int sc = 0; sc < 32; sc++) {
        const float2* p = reinterpret_cast<const float2*>(
            g_ctx_part + (size_t)(sc * B_ + b) * D_) + t;
        float2 v = *p;
        sx += v.x;
        sy += v.y;
    }
    float2* dst = reinterpret_cast<float2*>(out + b * D_) + t;
    *dst = make_float2(sx, sy);
}

// ---------------------------------------------------------------------------
// Launch. Inputs: decoder_output, encoder_output, W_t, b_t, v_a, b_v(unused)
// out: [0, B*D) context, [B*D, B*D+B*S) alignment
// ---------------------------------------------------------------------------
extern "C" void kernel_launch(void* const* d_in, const int* in_sizes, int n_in,
                              void* d_out, int out_size) {
    const float* dec = (const float*)d_in[0];
    const float* enc = (const float*)d_in[1];
    const float* Wt  = (const float*)d_in[2];
    const float* bt  = (const float*)d_in[3];
    const float* va  = (const float*)d_in[4];
    float* out = (float*)d_out;

    static int attr_set = 0;
    if (!attr_set) {
        cudaFuncSetAttribute(score_kernel,
                             cudaFuncAttributeMaxDynamicSharedMemorySize,
                             SMEM_TOTAL);
        attr_set = 1;
    }

    decpart_kernel<<<dim3(4, B_), 128>>>(dec, Wt, bt);
    wconv_kernel<<<512, 512>>>(Wt);
    encconv_kernel<<<(B_ * S_ * D_ / 4) / 512, 256>>>(enc);
    score_kernel<<<dim3(64, B_), 256, SMEM_TOTAL>>>(va);
    softmax_kernel<<<B_, 512>>>(out);
    ctx_part_kernel<<<dim3(32, B_), 256>>>(out);
    ctx_combine_kernel<<<B_, 256>>>(out);
}

// round 17
// speedup vs baseline: 1.3848x; 1.3848x over previous
#include <cuda_runtime.h>
#include <cuda_fp16.h>
#include <math.h>
#include <stdint.h>

#define B_ 64
#define S_ 2048
#define D_ 512

// ---------------- scratch (static device globals) ----------------
__device__ float g_dec_part[B_ * D_];
__device__ float g_score_part[4 * B_ * S_];
__device__ __align__(16) __half g_WT[D_ * D_];           // W_enc^T fp16, [n][k]
__device__ __align__(16) __half g_EncH[B_ * S_ * D_];    // enc fp16, 128 MB
__device__ float g_ctx_part[32 * B_ * D_];

// ---------------- helpers ----------------
__device__ __forceinline__ uint32_t smem_u32(const void* p) {
    uint32_t a;
    asm("{ .reg .u64 t; cvta.to.shared.u64 t, %1; cvt.u32.u64 %0, t; }"
        : "=r"(a) : "l"(p));
    return a;
}

__device__ __forceinline__ void ldsm4(uint32_t* r, uint32_t addr) {
    asm volatile("ldmatrix.sync.aligned.m8n8.x4.shared.b16 {%0,%1,%2,%3}, [%4];"
                 : "=r"(r[0]), "=r"(r[1]), "=r"(r[2]), "=r"(r[3]) : "r"(addr));
}

__device__ __forceinline__ void mma16816(float* c, const uint32_t* a,
                                         const uint32_t* b) {
    asm volatile(
        "mma.sync.aligned.m16n8k16.row.col.f32.f16.f16.f32 "
        "{%0,%1,%2,%3}, {%4,%5,%6,%7}, {%8,%9}, {%0,%1,%2,%3};"
        : "+f"(c[0]), "+f"(c[1]), "+f"(c[2]), "+f"(c[3])
        : "r"(a[0]), "r"(a[1]), "r"(a[2]), "r"(a[3]), "r"(b[0]), "r"(b[1]));
}

__device__ __forceinline__ uint32_t pack_h2(__half a, __half b) {
    __half2 t = __halves2half2(a, b);
    return *reinterpret_cast<uint32_t*>(&t);
}

#define CP_ASYNC16(dst, src) \
    asm volatile("cp.async.cg.shared.global [%0], [%1], 16;" :: "r"(dst), "l"(src))
#define CP_COMMIT()  asm volatile("cp.async.commit_group;")
#define CP_WAIT0()   asm volatile("cp.async.wait_group 0;")
#define CP_WAIT1()   asm volatile("cp.async.wait_group 1;")

// ---------------------------------------------------------------------------
// Kernel 1: dec_part[b][d] = b_t[d] + dec[b] @ W_t[:D]   (fp32, exact)
// ---------------------------------------------------------------------------
__global__ void decpart_kernel(const float* __restrict__ dec,
                               const float* __restrict__ Wt,
                               const float* __restrict__ bt) {
    __shared__ float ds[D_];
    int b = blockIdx.y;
    int d = blockIdx.x * 128 + threadIdx.x;
    for (int i = threadIdx.x; i < D_; i += 128) ds[i] = dec[b * D_ + i];
    __syncthreads();
    float acc = bt[d];
#pragma unroll 8
    for (int e = 0; e < D_; e++)
        acc = fmaf(ds[e], Wt[(size_t)e * D_ + d], acc);
    g_dec_part[b * D_ + d] = acc;
}

// ---------------------------------------------------------------------------
// Kernel 2: W_enc -> fp16, transposed to [n][k]
// ---------------------------------------------------------------------------
__global__ void wconv_kernel(const float* __restrict__ Wt) {
    int idx = blockIdx.x * 512 + threadIdx.x;  // idx = k*512 + n
    int k = idx >> 9;
    int n = idx & 511;
    g_WT[(size_t)n * D_ + k] = __float2half_rn(Wt[(size_t)(D_ + k) * D_ + n]);
}

// ---------------------------------------------------------------------------
// Kernel 2b: enc -> fp16, 8 floats (2 x float4) per thread
// ---------------------------------------------------------------------------
__global__ void encconv_kernel(const float* __restrict__ enc) {
    size_t base = (size_t)blockIdx.x * 512 + threadIdx.x;   // float4 index
#pragma unroll
    for (int j = 0; j < 2; j++) {
        size_t i4 = base + j * 256;
        float4 v = reinterpret_cast<const float4*>(enc)[i4];
        reinterpret_cast<uint2*>(g_EncH)[i4] = make_uint2(
            pack_h2(__float2half_rn(v.x), __float2half_rn(v.y)),
            pack_h2(__float2half_rn(v.z), __float2half_rn(v.w)));
    }
}

// ---------------------------------------------------------------------------
// Kernel 3: score GEMM, pure fp16 mma.sync, 3-stage cp.async ring, occ 2.
// CTA: M=128 x N=128, K=512 in 16 chunks of 32. 8 warps 2m x 4n, warp 64x32.
// (Verbatim R8/R13 — proven fastest configuration; loads issued BEFORE the
// MMA body, which R15 proved is load-bearing.)
// ---------------------------------------------------------------------------
#define STRIDE 80          // bytes per 32-elem fp16 row (64B data + 16B pad)
#define A_OFF 0
#define B_OFF 10240
#define STAGE_SZ 20480
#define DEC_OFF 61440
#define VA_OFF  63488
#define RED_OFF 65536
#define SMEM_TOTAL 67584

__global__ __launch_bounds__(256, 2)
void score_kernel(const float* __restrict__ va) {
    extern __shared__ __align__(16) char sm[];
    float* sDec = reinterpret_cast<float*>(sm + DEC_OFF);
    float* sVa  = reinterpret_cast<float*>(sm + VA_OFF);
    float* sRed = reinterpret_cast<float*>(sm + RED_OFF);

    int tid = threadIdx.x;
    int l = tid & 31;
    int w = tid >> 5;
    int warpm = w >> 2;
    int warpn = w & 3;
    int b  = blockIdx.y;
    int nc = blockIdx.x & 3;            // n-chunk (fastest -> co-scheduled)
    int s0 = (blockIdx.x >> 2) * 128;   // s-chunk

    sDec[tid]       = g_dec_part[b * D_ + tid];
    sDec[tid + 256] = g_dec_part[b * D_ + tid + 256];
    sVa[tid]        = va[tid];
    sVa[tid + 256]  = va[tid + 256];

    const __half* eh = g_EncH + ((size_t)b * S_ + s0) * D_;
    const __half* wh = g_WT + (size_t)(nc * 128) * D_;

    uint32_t smU = smem_u32(sm);
    uint32_t aOff = warpm * (64 * STRIDE) + (l & 15) * STRIDE + (l >> 4) * 16;
    uint32_t bOff = warpn * (32 * STRIDE)
                  + ((l & 7) + ((l & 16) >> 1)) * STRIDE + (l & 8) * 2;

    // per-thread cp.async: 2 chunks per tile; rows r0, r0+64; 16B col c0
    int r0 = tid >> 2;
    int r1 = r0 + 64;
    int c0 = (tid & 3) * 16;
    int k0e0 = (tid & 3) * 8;

    // ---- prologue: load stages 0 and 1 (kc = 0, 1) ----
#pragma unroll
    for (int s = 0; s < 2; s++) {
        uint32_t sb = smU + s * STAGE_SZ;
        int ke = s * 32 + k0e0;
        CP_ASYNC16(sb + A_OFF + r0 * STRIDE + c0, eh + (size_t)r0 * D_ + ke);
        CP_ASYNC16(sb + A_OFF + r1 * STRIDE + c0, eh + (size_t)r1 * D_ + ke);
        CP_ASYNC16(sb + B_OFF + r0 * STRIDE + c0, wh + (size_t)r0 * D_ + ke);
        CP_ASYNC16(sb + B_OFF + r1 * STRIDE + c0, wh + (size_t)r1 * D_ + ke);
        CP_COMMIT();
    }

    float acc[4][4][4];
#pragma unroll
    for (int mf = 0; mf < 4; mf++)
#pragma unroll
        for (int nf = 0; nf < 4; nf++)
#pragma unroll
            for (int r = 0; r < 4; r++) acc[mf][nf][r] = 0.f;

    for (int kc = 0; kc < 16; kc++) {
        if (kc < 15) { CP_WAIT1(); } else { CP_WAIT0(); }
        __syncthreads();   // stage kc%3 visible; slot (kc+2)%3 free of readers

        uint32_t curBase = smU + (kc % 3) * STAGE_SZ;

        // ---- issue loads for kc+2 into ring slot (kc+2)%3 ----
        if (kc + 2 < 16) {
            uint32_t nb = smU + ((kc + 2) % 3) * STAGE_SZ;
            int ke = (kc + 2) * 32 + k0e0;
            CP_ASYNC16(nb + A_OFF + r0 * STRIDE + c0, eh + (size_t)r0 * D_ + ke);
            CP_ASYNC16(nb + A_OFF + r1 * STRIDE + c0, eh + (size_t)r1 * D_ + ke);
            CP_ASYNC16(nb + B_OFF + r0 * STRIDE + c0, wh + (size_t)r0 * D_ + ke);
            CP_ASYNC16(nb + B_OFF + r1 * STRIDE + c0, wh + (size_t)r1 * D_ + ke);
            CP_COMMIT();
        }

        // ---- MMAs on current stage: 2 x k16 steps ----
#pragma unroll
        for (int ks = 0; ks < 2; ks++) {
            uint32_t kby = ks * 32;
            uint32_t a[4][4], bf[2][4];
#pragma unroll
            for (int mf = 0; mf < 4; mf++)
                ldsm4(a[mf], curBase + A_OFF + aOff + mf * (16 * STRIDE) + kby);
#pragma unroll
            for (int bp = 0; bp < 2; bp++)
                ldsm4(bf[bp], curBase + B_OFF + bOff + bp * (16 * STRIDE) + kby);
#pragma unroll
            for (int mf = 0; mf < 4; mf++)
#pragma unroll
                for (int nf = 0; nf < 4; nf++)
                    mma16816(acc[mf][nf], a[mf], &bf[nf >> 1][(nf & 1) * 2]);
        }
    }

    // ---- epilogue: tanh + dot v_a over this CTA's 128 d's ----
    float rp[8];
#pragma unroll
    for (int i = 0; i < 8; i++) rp[i] = 0.f;
    {
        int tig = l & 3;
#pragma unroll
        for (int mf = 0; mf < 4; mf++)
#pragma unroll
            for (int nf = 0; nf < 4; nf++)
#pragma unroll
                for (int r = 0; r < 4; r++) {
                    int d = nc * 128 + warpn * 32 + nf * 8 + tig * 2 + (r & 1);
                    float x = acc[mf][nf][r] + sDec[d];
                    float t = 1.0f - __fdividef(2.0f, __expf(2.0f * x) + 1.0f);
                    rp[mf * 2 + (r >> 1)] += t * sVa[d];
                }
    }
#pragma unroll
    for (int i = 0; i < 8; i++) {
        rp[i] += __shfl_xor_sync(0xffffffffu, rp[i], 1);
        rp[i] += __shfl_xor_sync(0xffffffffu, rp[i], 2);
    }
    __syncthreads();
    if ((l & 3) == 0) {
        int g = l >> 2;
#pragma unroll
        for (int mf = 0; mf < 4; mf++)
#pragma unroll
            for (int h = 0; h < 2; h++) {
                int row = warpm * 64 + mf * 16 + h * 8 + g;
                sRed[warpn * 128 + row] = rp[mf * 2 + h];
            }
    }
    __syncthreads();
    if (tid < 128)
        g_score_part[((size_t)nc * B_ + b) * S_ + s0 + tid] =
            sRed[tid] + sRed[128 + tid] + sRed[256 + tid] + sRed[384 + tid];
}

// ---------------------------------------------------------------------------
// Kernel 4: combine nc-partials + per-batch softmax -> alignment
// ---------------------------------------------------------------------------
__global__ void softmax_kernel(float* __restrict__ out) {
    int b = blockIdx.x;
    int t = threadIdx.x;
    __shared__ float red[16];

    float v[4];
    float mx = -1e30f;
#pragma unroll
    for (int i = 0; i < 4; i++) {
        int off = b * S_ + t + i * 512;
        v[i] = g_score_part[off]
             + g_score_part[(size_t)B_ * S_ + off]
             + g_score_part[(size_t)2 * B_ * S_ + off]
             + g_score_part[(size_t)3 * B_ * S_ + off];
        mx = fmaxf(mx, v[i]);
    }
    for (int off = 16; off > 0; off >>= 1)
        mx = fmaxf(mx, __shfl_xor_sync(0xffffffffu, mx, off));
    if ((t & 31) == 0) red[t >> 5] = mx;
    __syncthreads();
    if (t < 16) {
        float mm = red[t];
        for (int off = 8; off > 0; off >>= 1)
            mm = fmaxf(mm, __shfl_xor_sync(0xffffu, mm, off));
        red[t] = mm;
    }
    __syncthreads();
    mx = red[0];
    __syncthreads();

    float e[4], sum = 0.f;
#pragma unroll
    for (int i = 0; i < 4; i++) {
        e[i] = __expf(v[i] - mx);
        sum += e[i];
    }
    for (int off = 16; off > 0; off >>= 1)
        sum += __shfl_xor_sync(0xffffffffu, sum, off);
    if ((t & 31) == 0) red[t >> 5] = sum;
    __syncthreads();
    if (t < 16) {
        float ss = red[t];
        for (int off = 8; off > 0; off >>= 1)
            ss += __shfl_xor_sync(0xffffu, ss, off);
        red[t] = ss;
    }
    __syncthreads();
    float inv = 1.f / red[0];
#pragma unroll
    for (int i = 0; i < 4; i++)
        out[B_ * D_ + b * S_ + t + i * 512] = e[i] * inv;
}

// ---------------------------------------------------------------------------
// Kernel 5: partial context over 64-row s-chunks, __half2 loads (256 thr)
// ---------------------------------------------------------------------------
__global__ void ctx_part_kernel(const float* __restrict__ out_alpha) {
    int sc = blockIdx.x;                 // 0..31
    int b  = blockIdx.y;
    int t  = threadIdx.x;                // 256; covers d-pair 2t, 2t+1
    __shared__ float as_[64];
    if (t < 64) as_[t] = out_alpha[B_ * D_ + b * S_ + sc * 64 + t];
    __syncthreads();
    float ax = 0.f, ay = 0.f;
    const __half2* eb = reinterpret_cast<const __half2*>(
        g_EncH + ((size_t)b * S_ + sc * 64) * D_) + t;
#pragma unroll 8
    for (int s = 0; s < 64; s++) {
        float2 v = __half22float2(eb[(size_t)s * (D_ / 2)]);
        float a = as_[s];
        ax = fmaf(a, v.x, ax);
        ay = fmaf(a, v.y, ay);
    }
    float* dst = g_ctx_part + (size_t)(sc * B_ + b) * D_ + 2 * t;
    dst[0] = ax;
    dst[1] = ay;
}

// ---------------------------------------------------------------------------
// Kernel 6: combine partials, 256 threads x float2 (coalesced 8B loads)
// ---------------------------------------------------------------------------
__global__ void ctx_combine_kernel(float* __restrict__ out) {
    int b = blockIdx.x;
    int t = threadIdx.x;                 // 256; covers d-pair 2t, 2t+1
    float sx = 0.f, sy = 0.f;
#pragma unroll
    for (int sc = 0; sc < 32; sc++) {
        const float2* p = reinterpret_cast<const float2*>(
            g_ctx_part + (size_t)(sc * B_ + b) * D_) + t;
        float2 v = *p;
        sx += v.x;
        sy += v.y;
    }
    float2* dst = reinterpret_cast<float2*>(out + b * D_) + t;
    *dst = make_float2(sx, sy);
}

// ---------------------------------------------------------------------------
// Launch. Inputs: decoder_output, encoder_output, W_t, b_t, v_a, b_v(unused)
// out: [0, B*D) context, [B*D, B*D+B*S) alignment
// ---------------------------------------------------------------------------
extern "C" void kernel_launch(void* const* d_in, const int* in_sizes, int n_in,
                              void* d_out, int out_size) {
    const float* dec = (const float*)d_in[0];
    const float* enc = (const float*)d_in[1];
    const float* Wt  = (const float*)d_in[2];
    const float* bt  = (const float*)d_in[3];
    const float* va  = (const float*)d_in[4];
    float* out = (float*)d_out;

    static int attr_set = 0;
    if (!attr_set) {
        cudaFuncSetAttribute(score_kernel,
                             cudaFuncAttributeMaxDynamicSharedMemorySize,
                             SMEM_TOTAL);
        attr_set = 1;
    }

    decpart_kernel<<<dim3(4, B_), 128>>>(dec, Wt, bt);
    wconv_kernel<<<512, 512>>>(Wt);
    encconv_kernel<<<(B_ * S_ * D_ / 4) / 512, 256>>>(enc);
    score_kernel<<<dim3(64, B_), 256, SMEM_TOTAL>>>(va);
    softmax_kernel<<<B_, 512>>>(out);
    ctx_part_kernel<<<dim3(32, B_), 256>>>(out);
    ctx_combine_kernel<<<B_, 256>>>(out);
}